// round 10
// baseline (speedup 1.0000x reference)
#include <cuda_runtime.h>
#include <cstdint>

#define Bq 8
#define Cc 256
#define NQ 4096
#define NK 4096
#define KK 8

// Scratch (device globals — no allocation allowed)
__device__ float g_kf_t[(size_t)Bq * NK * Cc];   // key_features transposed [b, m, c]
__device__ float g_qf_t[(size_t)Bq * NQ * Cc];   // query_features transposed [b, n, c]
__device__ int   g_idx[(size_t)Bq * NQ * KK];    // knn indices

#define KNN_BLOCKS   (Bq * (NQ / 256))                    // 128
#define T_BLOCKS     ((NQ / 32) * (Cc / 32) * 2 * Bq)     // 16384
#define BC_BLOCKS    (Bq * Cc)                            // 2048
#define KCHUNK 2048

// ---------------------------------------------------------------------------
// Fused kernel 1: heterogeneous grid.
//   blocks [0, 128):            kNN (fat, issue-bound, one per SM — lands
//                               first via in-order placement)
//   blocks [128, 128+16384):    feature transposes (qf & kf)
//   blocks [16512, 18560):      broadcast half of output:
//                               out[b, C+c, n, k] = qf[b, c, n]
// All three roles are mutually independent. Memory-bound roles hide behind
// the 150us knn. Shared smem buffer: 32KB (knn key cache / transpose tile).
// ---------------------------------------------------------------------------
__global__ void __launch_bounds__(256, 4)
fused1_kernel(const float* __restrict__ qc, const float* __restrict__ kc,
              const float* __restrict__ qf, const float* __restrict__ kf,
              float* __restrict__ qf_t, float* __restrict__ kf_t,
              float* __restrict__ out) {
    __shared__ float4 sbuf[KCHUNK];   // 32 KB
    const int bid = blockIdx.x;
    const int t   = threadIdx.x;

    if (bid < KNN_BLOCKS) {
        // ------------------- kNN (bitwise-verified, R6 verbatim) ----------
        float4* skey = sbuf;
        const int b  = bid / (NQ / 256);
        const int n0 = (bid % (NQ / 256)) * 256;
        const int n  = n0 + t;

        const float* kcb = kc + (size_t)b * 3 * NK;
        const float* qcb = qc + (size_t)b * 3 * NQ;

        const float qx = qcb[n];
        const float qy = qcb[NQ + n];
        const float qz = qcb[2 * NQ + n];
        const float sq = fmaf(qz, qz, fmaf(qy, qy, __fmul_rn(qx, qx)));

        float bd[KK];
        int   bi[KK];
#pragma unroll
        for (int j = 0; j < KK; j++) { bd[j] = 3.4e38f; bi[j] = 0; }

        for (int chunk = 0; chunk < NK; chunk += KCHUNK) {
            __syncthreads();
            for (int m = t; m < KCHUNK; m += 256) {
                const int gm = chunk + m;
                const float x = kcb[gm];
                const float y = kcb[NK + gm];
                const float z = kcb[2 * NK + gm];
                const float skk = fmaf(z, z, fmaf(y, y, __fmul_rn(x, x)));
                skey[m] = make_float4(x, y, z, skk);
            }
            __syncthreads();

            for (int m = 0; m < KCHUNK; m += 4) {
#pragma unroll
                for (int u = 0; u < 4; u++) {
                    const float4 kv = skey[m + u];        // broadcast LDS
                    const float cross = fmaf(qz, kv.z,
                                        fmaf(qy, kv.y,
                                             __fmul_rn(qx, kv.x)));
                    const float tt = __fadd_rn(sq, -2.0f * cross);
                    const float d  = __fadd_rn(tt, kv.w);
                    if (d < bd[KK - 1]) {                 // rare
                        float cd = d; int ci = chunk + m + u;
#pragma unroll
                        for (int j = 0; j < KK; j++) {
                            const bool sw = cd < bd[j];
                            const float td = bd[j]; const int ti = bi[j];
                            bd[j] = sw ? cd : td;  bi[j] = sw ? ci : ti;
                            cd    = sw ? td : cd;  ci    = sw ? ti : ci;
                        }
                    }
                }
            }
        }

        int* o = g_idx + ((size_t)b * NQ + n) * KK;
#pragma unroll
        for (int j = 0; j < KK; j++) o[j] = bi[j];

    } else if (bid < KNN_BLOCKS + T_BLOCKS) {
        // ------------------- transpose [B,C,N] -> [B,N,C] ------------------
        float (*tile)[33] = reinterpret_cast<float(*)[33]>(sbuf);
        const int local = bid - KNN_BLOCKS;
        const int z   = local / ((NQ / 32) * (Cc / 32));   // 0..15
        const int r   = local % ((NQ / 32) * (Cc / 32));
        const int c0  = (r / (NQ / 32)) * 32;
        const int n0  = (r % (NQ / 32)) * 32;
        const int b   = z & 7;
        const float* in  = (z >> 3) ? kf   : qf;
        float*       outp = (z >> 3) ? kf_t : qf_t;
        const float* inb  = in  + (size_t)b * Cc * NQ;
        float*       outb = outp + (size_t)b * Cc * NQ;
        const int tx = t & 31;
        const int ty = t >> 5;     // 0..7
#pragma unroll
        for (int j = 0; j < 32; j += 8)
            tile[ty + j][tx] = inb[(size_t)(c0 + ty + j) * NQ + (n0 + tx)];
        __syncthreads();
#pragma unroll
        for (int j = 0; j < 32; j += 8)
            outb[(size_t)(n0 + ty + j) * Cc + (c0 + tx)] = tile[tx][ty + j];

    } else {
        // ------------------- broadcast half: out[b,C+c,n,:] = qf[b,c,n] ----
        const int local = bid - (KNN_BLOCKS + T_BLOCKS);
        const int b = local >> 8;
        const int c = local & (Cc - 1);
        const float* src = qf + ((size_t)b * Cc + c) * NQ;
        float* dst = out + (((size_t)b * (2 * Cc) + Cc + c) * NQ) * KK;
#pragma unroll 4
        for (int i = t; i < NQ; i += 256) {
            const float v = src[i];                 // coalesced 1KB/warp
            const float4 v4 = make_float4(v, v, v, v);
            __stcs(reinterpret_cast<float4*>(dst + (size_t)i * KK), v4);
            __stcs(reinterpret_cast<float4*>(dst + (size_t)i * KK + 4), v4);
        }
    }
}

// ---------------------------------------------------------------------------
// Gather kernel: diff half only. Block = 4 queries x 8 neighbors = 32 slots.
// Stage 32 neighbor rows + 4 query rows in padded smem; STG.128 streaming
// stores (evict-first) of neighbor - query to out[b, c, n, k], c < 256.
// ---------------------------------------------------------------------------
#define NT 4
#define SLOTS (NT * KK)      // 32
#define PADN 257
#define PADQ 260

__global__ void __launch_bounds__(256, 6)
gather_kernel(float* __restrict__ out) {
    __shared__ int   sidx[SLOTS];
    __shared__ float sn[SLOTS * PADN];   // ~32.9 KB
    __shared__ float sq[NT * PADQ];      // ~4.1 KB

    const int b  = blockIdx.x / (NQ / NT);
    const int n0 = (blockIdx.x % (NQ / NT)) * NT;
    const int t  = threadIdx.x;

    if (t < SLOTS)
        sidx[t] = g_idx[((size_t)b * NQ + n0) * KK + t];

    // stage query rows [NT][C]
    for (int i = t; i < NT * Cc; i += 256) {
        const int r = i >> 8;           // /C
        const int c = i & (Cc - 1);
        sq[r * PADQ + c] = g_qf_t[((size_t)b * NQ + n0 + r) * Cc + c];
    }
    __syncthreads();

    // gather neighbor rows: 32 x 1KB coalesced loads (L2-resident kf_t)
#pragma unroll
    for (int r = 0; r < SLOTS; r++) {
        sn[r * PADN + t] = g_kf_t[((size_t)b * NK + sidx[r]) * Cc + t];
    }
    __syncthreads();

    // write phase: thread owns slot quad q (slots 4q..4q+3, same query) and
    // channel c = ci*32 + cg; conflict-free LDS, one STG.128 per iter.
    const int q  = t & 7;               // slot quad 0..7
    const int cg = t >> 3;              // 0..31
    const int s0 = 4 * q;
    const int nloc = q >> 1;            // local query index

#pragma unroll
    for (int ci = 0; ci < 8; ci++) {
        const int c = ci * 32 + cg;
        const float qv = sq[nloc * PADQ + c];
        const float v0 = sn[(s0 + 0) * PADN + c];
        const float v1 = sn[(s0 + 1) * PADN + c];
        const float v2 = sn[(s0 + 2) * PADN + c];
        const float v3 = sn[(s0 + 3) * PADN + c];

        const size_t baseD = (((size_t)b * (2 * Cc) + c) * NQ + n0) * KK + s0;
        __stcs(reinterpret_cast<float4*>(out + baseD),
               make_float4(v0 - qv, v1 - qv, v2 - qv, v3 - qv));
    }
}

// ---------------------------------------------------------------------------
extern "C" void kernel_launch(void* const* d_in, const int* in_sizes, int n_in,
                              void* d_out, int out_size) {
    const float* query_coords   = (const float*)d_in[0];
    const float* query_features = (const float*)d_in[1];
    const float* key_coords     = (const float*)d_in[2];
    const float* key_features   = (const float*)d_in[3];
    float* out = (float*)d_out;

    float* kf_t; cudaGetSymbolAddress((void**)&kf_t, g_kf_t);
    float* qf_t; cudaGetSymbolAddress((void**)&qf_t, g_qf_t);

    fused1_kernel<<<KNN_BLOCKS + T_BLOCKS + BC_BLOCKS, 256>>>(
        query_coords, key_coords, query_features, key_features,
        qf_t, kf_t, out);

    gather_kernel<<<Bq * (NQ / NT), 256>>>(out);
}

// round 12
// speedup vs baseline: 1.2854x; 1.2854x over previous
#include <cuda_runtime.h>
#include <cstdint>

#define Bq 8
#define Cc 256
#define NQ 4096
#define NK 4096
#define KK 8

// Scratch (device globals — no allocation allowed)
__device__ float g_kf_t[(size_t)Bq * NK * Cc];   // key_features transposed [b, m, c]
__device__ int   g_idx[(size_t)Bq * NQ * KK];    // knn indices

// ---------------------------------------------------------------------------
// Transpose key_features [B, C, N] -> [B, N, C]
// ---------------------------------------------------------------------------
__global__ void transpose_kernel(const float* __restrict__ in, float* __restrict__ out) {
    __shared__ float tile[32][33];
    const int b  = blockIdx.z;
    const int n0 = blockIdx.x * 32;
    const int c0 = blockIdx.y * 32;
    const float* inb  = in  + (size_t)b * Cc * NQ;
    float*       outb = out + (size_t)b * Cc * NQ;
    const int tx = threadIdx.x;   // 0..31
    const int ty = threadIdx.y;   // 0..7
#pragma unroll
    for (int j = 0; j < 32; j += 8)
        tile[ty + j][tx] = inb[(size_t)(c0 + ty + j) * NQ + (n0 + tx)];
    __syncthreads();
#pragma unroll
    for (int j = 0; j < 32; j += 8)
        outb[(size_t)(n0 + ty + j) * Cc + (c0 + tx)] = tile[tx][ty + j];
}

// ---------------------------------------------------------------------------
// kNN (R6 verbatim — bitwise-verified arithmetic, rel_err 0.0):
//   cross = fma(qz,kz, fma(qy,ky, rn(qx*kx)))   sq/sk same fma-ascending
//   d     = rn(rn(sq - 2*cross) + sk)
// Ties: strict '<' insertion keeps earlier index first (matches top_k).
// ---------------------------------------------------------------------------
#define KCHUNK 2048

__global__ void __launch_bounds__(256, 1)
knn_kernel(const float* __restrict__ qc, const float* __restrict__ kc) {
    __shared__ float4 skey[KCHUNK];   // 32 KB: (kx, ky, kz, |k|^2)

    const int b  = blockIdx.x / (NQ / 256);
    const int n0 = (blockIdx.x % (NQ / 256)) * 256;
    const int n  = n0 + threadIdx.x;

    const float* kcb = kc + (size_t)b * 3 * NK;
    const float* qcb = qc + (size_t)b * 3 * NQ;

    const float qx = qcb[n];
    const float qy = qcb[NQ + n];
    const float qz = qcb[2 * NQ + n];
    const float sq = fmaf(qz, qz, fmaf(qy, qy, __fmul_rn(qx, qx)));

    float bd[KK];
    int   bi[KK];
#pragma unroll
    for (int j = 0; j < KK; j++) { bd[j] = 3.4e38f; bi[j] = 0; }

    for (int chunk = 0; chunk < NK; chunk += KCHUNK) {
        __syncthreads();
        for (int m = threadIdx.x; m < KCHUNK; m += 256) {
            const int gm = chunk + m;
            const float x = kcb[gm];
            const float y = kcb[NK + gm];
            const float z = kcb[2 * NK + gm];
            const float skk = fmaf(z, z, fmaf(y, y, __fmul_rn(x, x)));
            skey[m] = make_float4(x, y, z, skk);
        }
        __syncthreads();

        for (int m = 0; m < KCHUNK; m += 4) {
#pragma unroll
            for (int u = 0; u < 4; u++) {
                const float4 kv = skey[m + u];            // uniform addr -> broadcast
                const float cross = fmaf(qz, kv.z,
                                    fmaf(qy, kv.y,
                                         __fmul_rn(qx, kv.x)));
                const float t = __fadd_rn(sq, -2.0f * cross);
                const float d = __fadd_rn(t, kv.w);
                if (d < bd[KK - 1]) {                     // rare
                    float cd = d; int ci = chunk + m + u;
#pragma unroll
                    for (int j = 0; j < KK; j++) {
                        const bool sw = cd < bd[j];
                        const float td = bd[j]; const int ti = bi[j];
                        bd[j] = sw ? cd : td;  bi[j] = sw ? ci : ti;
                        cd    = sw ? td : cd;  ci    = sw ? ti : ci;
                    }
                }
            }
        }
    }

    int* o = g_idx + ((size_t)b * NQ + n) * KK;
#pragma unroll
    for (int j = 0; j < KK; j++) o[j] = bi[j];
}

// ---------------------------------------------------------------------------
// Output kernel: tile = 32 queries x 32 channels. Each warp owns a channel
// and writes CONTIGUOUS 1KB spans for both halves:
//   out[b, c,     n, k] = kf_t[sidx[n,k], c] - qf[b, c, n]
//   out[b, C + c, n, k] = qf[b, c, n]
// sn stored channel-major so write-phase reads are LDS.128.
// ---------------------------------------------------------------------------
#define TQ 32               // queries per tile
#define TC 32               // channels per tile
#define ROWS (TQ * KK)      // 256 gathered rows
#define SNPAD 260           // row-dim stride (16B-aligned for LDS.128)
#define SQPAD 33

__global__ void __launch_bounds__(256, 5)
gather_kernel(const float* __restrict__ qf, float* __restrict__ out) {
    __shared__ float sn[TC * SNPAD];     // 33.3 KB  [c][row]
    __shared__ float sqv[TC * SQPAD];    // 4.2 KB   [c][q]
    __shared__ int   sidx[ROWS];         // 1 KB

    const int bid = blockIdx.x;
    const int b   = bid >> 10;
    const int rem = bid & 1023;
    const int cg  = rem >> 7;            // 0..7  -> c0 = 32*cg
    const int nc  = rem & 127;           // 0..127 -> n0 = 32*nc
    const int c0  = cg * TC;
    const int n0  = nc * TQ;
    const int t   = threadIdx.x;

    // stage indices: row r = q*8 + k
    sidx[t] = g_idx[((size_t)b * NQ + n0) * KK + t];

    // stage query values sqv[c][q] from qf[b, c0+c, n0+q] (coalesced in q)
#pragma unroll
    for (int it = 0; it < 4; it++) {
        const int cl = (t >> 5) + 8 * it;
        const int q  = t & 31;
        sqv[cl * SQPAD + q] = qf[((size_t)b * Cc + c0 + cl) * NQ + n0 + q];
    }
    __syncthreads();

    // gather neighbor rows into sn[c][row]: 256 rows x 32 channels.
    // i -> (row = i>>3, c4 = i&7): warp reads 4 rows x 128B coalesced.
    const float4* kf4 = reinterpret_cast<const float4*>(g_kf_t);
#pragma unroll
    for (int it = 0; it < 8; it++) {
        const int i  = t + it * 256;
        const int r  = i >> 3;
        const int c4 = i & 7;
        const int row = sidx[r];
        const float4 v = kf4[((size_t)b * NK + row) * (Cc / 4) + cg * 8 + c4];
        sn[(c4 * 4 + 0) * SNPAD + r] = v.x;
        sn[(c4 * 4 + 1) * SNPAD + r] = v.y;
        sn[(c4 * 4 + 2) * SNPAD + r] = v.z;
        sn[(c4 * 4 + 3) * SNPAD + r] = v.w;
    }
    __syncthreads();

    // write phase: warp w handles channels cl = w + 8*citer.
    // Each channel span = 256 floats = 64 float4; p = j*32 + lane (j<2).
    // Rows 4p..4p+3 share query q = p>>1. Contiguous STG.128 per warp.
    const int w    = t >> 5;
    const int lane = t & 31;

#pragma unroll
    for (int citer = 0; citer < 4; citer++) {
        const int cl = w + 8 * citer;
        const int c  = c0 + cl;
        const size_t baseD = ((size_t)b * (2 * Cc) + c) * ((size_t)NQ * KK) + (size_t)n0 * KK;
        const size_t baseB = ((size_t)b * (2 * Cc) + Cc + c) * ((size_t)NQ * KK) + (size_t)n0 * KK;
#pragma unroll
        for (int j = 0; j < 2; j++) {
            const int p = j * 32 + lane;           // 0..63
            const float4 v = *reinterpret_cast<const float4*>(&sn[cl * SNPAD + 4 * p]);
            const float qv = sqv[cl * SQPAD + (p >> 1)];
            __stcs(reinterpret_cast<float4*>(out + baseD + 4 * p),
                   make_float4(v.x - qv, v.y - qv, v.z - qv, v.w - qv));
            __stcs(reinterpret_cast<float4*>(out + baseB + 4 * p),
                   make_float4(qv, qv, qv, qv));
        }
    }
}

// ---------------------------------------------------------------------------
extern "C" void kernel_launch(void* const* d_in, const int* in_sizes, int n_in,
                              void* d_out, int out_size) {
    const float* query_coords   = (const float*)d_in[0];
    const float* query_features = (const float*)d_in[1];
    const float* key_coords     = (const float*)d_in[2];
    const float* key_features   = (const float*)d_in[3];
    float* out = (float*)d_out;

    float* kf_t; cudaGetSymbolAddress((void**)&kf_t, g_kf_t);

    dim3 tgrid(NQ / 32, Cc / 32, Bq);
    dim3 tblk(32, 8);
    transpose_kernel<<<tgrid, tblk>>>(key_features, kf_t);

    knn_kernel<<<Bq * (NQ / 256), 256>>>(query_coords, key_coords);

    gather_kernel<<<Bq * (Cc / TC) * (NQ / TQ), 256>>>(query_features, out);
}